// round 3
// baseline (speedup 1.0000x reference)
#include <cuda_runtime.h>
#include <math.h>

#define NTH 256
#define TB  64
#define SWS 132   // weight smem stride (floats)
#define HS  132   // activation smem stride (floats)

// ---- smem layout (float offsets) ----
#define OFF_W    0
#define OFF_H1   (OFF_W   + 128*SWS)
#define OFF_H2   (OFF_H1  + TB*HS)
#define OFF_U    (OFF_H2  + TB*HS)
#define OFF_W1L  (OFF_U   + TB*HS)
#define OFF_W1V  (OFF_W1L + 12*SWS)
#define OFF_W3L  (OFF_W1V + 12*SWS)
#define OFF_W3V  (OFF_W3L + 128*21)
#define OFF_B1L  (OFF_W3V + 128)
#define OFF_B2L  (OFF_B1L + 128)
#define OFF_B3L  (OFF_B2L + 128)
#define OFF_B1V  (OFF_B3L + 24)
#define OFF_B2V  (OFF_B1V + 128)
#define OFF_X    (OFF_B2V + 128)
#define OFF_Q    (OFF_X   + TB*12)
#define OFF_QD   (OFF_Q   + TB*6)
#define OFF_A    (OFF_QD  + TB*6)
#define OFF_K1   (OFF_A   + TB*6)
#define OFF_M    (OFF_K1  + TB*6)
#define OFF_L    (OFF_M   + TB*36)
#define OFF_DY   (OFF_L   + TB*21)
#define OFF_QDD  (OFF_DY  + TB*21)
#define SMEM_FLOATS (OFF_QDD + TB*6)

static __device__ __forceinline__ float softplusf(float z) {
    return fmaxf(z, 0.0f) + __logf(1.0f + __expf(-fabsf(z)));
}
// sigmoid(z) given h = softplus(z):  sigma = 1 - exp(-h)   (h >= 0)
static __device__ __forceinline__ float sig_from_h(float h) {
    return 1.0f - __expf(-h);
}
static __device__ __forceinline__ float f4c(const float4& v, int k) {
    return k == 0 ? v.x : k == 1 ? v.y : k == 2 ? v.z : v.w;
}

extern "C" __global__ void __launch_bounds__(NTH, 1)
lnn6dof_kernel(const float* __restrict__ o,    const float* __restrict__ ain,
               const float* __restrict__ gW1L, const float* __restrict__ gb1L,
               const float* __restrict__ gW2L, const float* __restrict__ gb2L,
               const float* __restrict__ gW3L, const float* __restrict__ gb3L,
               const float* __restrict__ gW1V, const float* __restrict__ gb1V,
               const float* __restrict__ gW2V, const float* __restrict__ gb2V,
               const float* __restrict__ gW3V,
               float* __restrict__ outp, int B)
{
    extern __shared__ float sm[];
    float* sW   = sm + OFF_W;
    float* sH1  = sm + OFF_H1;
    float* sH2  = sm + OFF_H2;
    float* sU   = sm + OFF_U;
    float* sW1L = sm + OFF_W1L;
    float* sW1V = sm + OFF_W1V;
    float* sW3L = sm + OFF_W3L;
    float* sW3V = sm + OFF_W3V;
    float* sB1L = sm + OFF_B1L;
    float* sB2L = sm + OFF_B2L;
    float* sB3L = sm + OFF_B3L;
    float* sB1V = sm + OFF_B1V;
    float* sB2V = sm + OFF_B2V;
    float* sX   = sm + OFF_X;
    float* sQ   = sm + OFF_Q;
    float* sQd  = sm + OFF_QD;
    float* sA   = sm + OFF_A;
    float* sK1  = sm + OFF_K1;
    float* sM   = sm + OFF_M;
    float* sL   = sm + OFF_L;
    float* sDY  = sm + OFF_DY;
    float* sQdd = sm + OFF_QDD;

    const int tid  = threadIdx.x;
    const int lane = tid & 31;
    const int r0   = (tid >> 5) * 8;   // warp's first local row
    const int c0   = lane * 4;         // lane's first output col

    // ---- persistent small weights ----
    for (int i = tid; i < 12 * 128; i += NTH) {
        int r = i >> 7, c = i & 127;
        sW1L[r * SWS + c] = gW1L[i];
        sW1V[r * SWS + c] = gW1V[i];
    }
    for (int i = tid; i < 128 * 21; i += NTH) sW3L[i] = gW3L[i];
    for (int i = tid; i < 128; i += NTH) {
        sW3V[i] = gW3V[i];
        sB1L[i] = gb1L[i]; sB2L[i] = gb2L[i];
        sB1V[i] = gb1V[i]; sB2V[i] = gb2V[i];
    }
    if (tid < 21) sB3L[tid] = gb3L[tid];

    const int base = blockIdx.x * TB;
    for (int i = tid; i < TB * 6; i += NTH) {
        int r = i / 6, c = i - 6 * r;
        int g = base + r; if (g > B - 1) g = B - 1;
        sQ[i]  = o[g * 18 + c];
        sQd[i] = o[g * 18 + 6 + c];
        sA[i]  = ain[g * 6 + c];
    }
    __syncthreads();

    // ---------- helpers (NO trailing sync inside; caller syncs) ----------
    // big GEMM: Out[r][c] = post( Ain[r][:] @ sW[:, c] (+ bias) )
    // post: mulSrc ? mulSrc[idx]*acc : softplus(acc)     (mulSrc already sigma!)
    auto bigGemm = [&](const float* Ain, const float* bias, float* Out,
                       const float* mulSrc, bool inplace) {
        float acc[8][4];
        if (bias) {
            float4 bv = *(const float4*)&bias[c0];
            #pragma unroll
            for (int rr = 0; rr < 8; rr++) {
                acc[rr][0] = bv.x; acc[rr][1] = bv.y;
                acc[rr][2] = bv.z; acc[rr][3] = bv.w;
            }
        } else {
            #pragma unroll
            for (int rr = 0; rr < 8; rr++)
                acc[rr][0] = acc[rr][1] = acc[rr][2] = acc[rr][3] = 0.f;
        }
        #pragma unroll 2
        for (int k = 0; k < 128; k += 4) {
            float4 av[8];
            #pragma unroll
            for (int rr = 0; rr < 8; rr++)
                av[rr] = *(const float4*)&Ain[(r0 + rr) * HS + k];
            #pragma unroll
            for (int kk = 0; kk < 4; kk++) {
                float4 wv = *(const float4*)&sW[(k + kk) * SWS + c0];
                #pragma unroll
                for (int rr = 0; rr < 8; rr++) {
                    float a = f4c(av[rr], kk);
                    acc[rr][0] += a * wv.x;
                    acc[rr][1] += a * wv.y;
                    acc[rr][2] += a * wv.z;
                    acc[rr][3] += a * wv.w;
                }
            }
        }
        if (inplace) __syncthreads();   // everyone done reading before overwrite
        #pragma unroll
        for (int rr = 0; rr < 8; rr++) {
            int rb = (r0 + rr) * HS + c0;
            float4 ov;
            if (mulSrc) {
                float4 mv = *(const float4*)&mulSrc[rb];
                ov.x = acc[rr][0] * mv.x; ov.y = acc[rr][1] * mv.y;
                ov.z = acc[rr][2] * mv.z; ov.w = acc[rr][3] * mv.w;
            } else {
                ov.x = softplusf(acc[rr][0]); ov.y = softplusf(acc[rr][1]);
                ov.z = softplusf(acc[rr][2]); ov.w = softplusf(acc[rr][3]);
            }
            *(float4*)&Out[rb] = ov;
        }
    };

    // K=12 GEMM from sX: Out = softplus(sX @ Wsm + bias)
    auto smallGemm = [&](const float* Wsm, const float* bias, float* Out) {
        float acc[8][4];
        float4 bv = *(const float4*)&bias[c0];
        #pragma unroll
        for (int rr = 0; rr < 8; rr++) {
            acc[rr][0] = bv.x; acc[rr][1] = bv.y;
            acc[rr][2] = bv.z; acc[rr][3] = bv.w;
        }
        #pragma unroll
        for (int k = 0; k < 12; k += 4) {
            float4 av[8];
            #pragma unroll
            for (int rr = 0; rr < 8; rr++)
                av[rr] = *(const float4*)&sX[(r0 + rr) * 12 + k];
            #pragma unroll
            for (int kk = 0; kk < 4; kk++) {
                float4 wv = *(const float4*)&Wsm[(k + kk) * SWS + c0];
                #pragma unroll
                for (int rr = 0; rr < 8; rr++) {
                    float a = f4c(av[rr], kk);
                    acc[rr][0] += a * wv.x; acc[rr][1] += a * wv.y;
                    acc[rr][2] += a * wv.z; acc[rr][3] += a * wv.w;
                }
            }
        }
        #pragma unroll
        for (int rr = 0; rr < 8; rr++) {
            int rb = (r0 + rr) * HS + c0;
            float4 ov;
            ov.x = softplusf(acc[rr][0]); ov.y = softplusf(acc[rr][1]);
            ov.z = softplusf(acc[rr][2]); ov.w = softplusf(acc[rr][3]);
            *(float4*)&Out[rb] = ov;
        }
    };

    // 128->21 GEMM with W3L : sDY[r*21+l] (lanes 0..20)
    auto mini21 = [&](const float* Ain, const float* bias) {
        if (lane < 21) {
            float acc[8];
            float b = bias ? bias[lane] : 0.f;
            #pragma unroll
            for (int rr = 0; rr < 8; rr++) acc[rr] = b;
            #pragma unroll 2
            for (int k = 0; k < 128; k += 4) {
                float4 av[8];
                #pragma unroll
                for (int rr = 0; rr < 8; rr++)
                    av[rr] = *(const float4*)&Ain[(r0 + rr) * HS + k];
                #pragma unroll
                for (int kk = 0; kk < 4; kk++) {
                    float wv = sW3L[(k + kk) * 21 + lane];
                    #pragma unroll
                    for (int rr = 0; rr < 8; rr++)
                        acc[rr] += f4c(av[rr], kk) * wv;
                }
            }
            #pragma unroll
            for (int rr = 0; rr < 8; rr++) sDY[(r0 + rr) * 21 + lane] = acc[rr];
        }
    };

    // tangent layer-1 input: sU = sig1 * (cq*W1L[2d+1] - sq*W1L[2d])
    auto buildU1 = [&](int d, int t, int nt) {
        for (int i = t; i < TB * 32; i += nt) {
            int r = i >> 5, c4 = (i & 31) << 2;
            float cq = sX[r * 12 + 2 * d];
            float sq = sX[r * 12 + 2 * d + 1];
            float4 w0 = *(const float4*)&sW1L[(2 * d) * SWS + c4];
            float4 w1 = *(const float4*)&sW1L[(2 * d + 1) * SWS + c4];
            float4 s1 = *(const float4*)&sH1[r * HS + c4];
            float4 ov;
            ov.x = s1.x * (cq * w1.x - sq * w0.x);
            ov.y = s1.y * (cq * w1.y - sq * w0.y);
            ov.z = s1.z * (cq * w1.z - sq * w0.z);
            ov.w = s1.w * (cq * w1.w - sq * w0.w);
            *(float4*)&sU[r * HS + c4] = ov;
        }
    };

    // convert h -> sigma(h) in place
    auto sigConvert = [&](float* P) {
        for (int i = tid; i < TB * 32; i += NTH) {
            float4* p = (float4*)&P[(i >> 5) * HS + ((i & 31) << 2)];
            float4 v = *p;
            v.x = 1.f - __expf(-v.x); v.y = 1.f - __expf(-v.y);
            v.z = 1.f - __expf(-v.z); v.w = 1.f - __expf(-v.w);
            *p = v;
        }
    };

    auto streamW = [&](const float* g) {     // row-major 128x128 -> sW
        for (int i = tid; i < 4096; i += NTH) {
            int r = i >> 5, c4 = (i & 31) << 2;
            *(float4*)&sW[r * SWS + c4] = *(const float4*)&g[i << 2];
        }
    };
    auto streamWT = [&](const float* g) {    // transposed -> sW
        for (int i = tid; i < 16384; i += NTH) {
            int r = i >> 7, c = i & 127;
            sW[c * SWS + r] = g[i];
        }
    };

    const float ADT = (2.0f / 3.0f) * 0.02f;
    const int RO[6] = {0, 1, 3, 6, 10, 15};

    for (int stage = 0; stage < 2; ++stage) {
        float wv6[6], Aacc[6], svec[6], Cacc[6], cvec[6];

        // R1: trig features + stream W2L
        for (int i = tid; i < TB * 6; i += NTH) {
            int r = i / 6, j = i - 6 * r;
            float sv, cv; __sincosf(sQ[i], &sv, &cv);
            sX[r * 12 + 2 * j]     = cv;
            sX[r * 12 + 2 * j + 1] = sv;
        }
        streamW(gW2L);
        __syncthreads();

        // R2: h1 = softplus(x @ W1L + b1L)
        smallGemm(sW1L, sB1L, sH1);
        __syncthreads();

        // R3: h2 = softplus(h1 @ W2L + b2L)
        bigGemm(sH1, sB2L, sH2, nullptr, false);
        __syncthreads();

        // R4: y = h2 @ W3L + b3L  ;  sH1 := sigma(h1)
        mini21(sH2, sB3L);
        sigConvert(sH1);
        __syncthreads();

        // R5: per-row L, M, w  ||  sH2 := sigma(h2)  ||  u1(dir 0)
        if (tid < TB) {
            const int r = tid;
            const float* y = sDY + r * 21;
            float* Lp = sL + r * 21;
            #pragma unroll
            for (int t = 0; t < 21; t++) Lp[t] = y[t];
            float* Mp = sM + r * 36;
            #pragma unroll
            for (int i = 0; i < 6; i++) {
                #pragma unroll
                for (int j = 0; j <= i; j++) {
                    float s2 = 0.f;
                    #pragma unroll
                    for (int k = 0; k <= j; k++)
                        s2 += Lp[RO[i] + k] * Lp[RO[j] + k];
                    if (i == j) s2 += 1e-6f;
                    Mp[i * 6 + j] = s2; Mp[j * 6 + i] = s2;
                }
            }
            #pragma unroll
            for (int i = 0; i < 6; i++) {
                float s2 = 0.f;
                #pragma unroll
                for (int j = 0; j < 6; j++) s2 += Mp[i * 6 + j] * sQd[r * 6 + j];
                wv6[i] = s2; Aacc[i] = 0.f; svec[i] = 0.f;
            }
        }
        sigConvert(sH2);
        if (tid >= 64) buildU1(0, tid - 64, NTH - 64);
        __syncthreads();

        // ---- 6 tangent directions ----
        for (int dir = 0; dir < 6; ++dir) {
            bigGemm(sU, nullptr, sU, sH2, true);   // u2 = sig2*(u1@W2L), in place
            __syncthreads();
            mini21(sU, nullptr);                   // dy
            if (dir == 5) streamW(gW2V);           // sW := W2V (W2L done)
            __syncthreads();

            if (tid < TB) {                        // epilogue(dir)
                const int r = tid;
                const float* dy  = sDY + r * 21;
                const float* Lp  = sL  + r * 21;
                const float* qdr = sQd + r * 6;
                float D[6][6];
                #pragma unroll
                for (int i = 0; i < 6; i++) {
                    #pragma unroll
                    for (int j = 0; j <= i; j++) {
                        float s2 = 0.f;
                        #pragma unroll
                        for (int k = 0; k <= j; k++)
                            s2 += dy[RO[i] + k] * Lp[RO[j] + k]
                                + Lp[RO[i] + k] * dy[RO[j] + k];
                        D[i][j] = s2; D[j][i] = s2;
                    }
                }
                float qdd = qdr[dir];
                float cdot = 0.f;
                #pragma unroll
                for (int i = 0; i < 6; i++) {
                    float v1 = 0.f, v2 = 0.f;
                    #pragma unroll
                    for (int j = 0; j < 6; j++) {
                        v1 += D[i][j] * wv6[j];
                        v2 += D[i][j] * qdr[j];
                    }
                    Aacc[i] += qdd * v1;
                    svec[i] += qdd * v2;
                    cdot    += qdr[i] * v1;
                }
                Cacc[dir] = cdot;
            }
            if (dir < 5) {
                if (tid >= 64) buildU1(dir + 1, tid - 64, NTH - 64);
            } else {
                smallGemm(sW1V, sB1V, sH1);        // h1V (all threads)
            }
            __syncthreads();
        }

        // h2V
        bigGemm(sH1, sB2V, sH2, nullptr, false);
        __syncthreads();

        // R9: u2g = sig(h2V)*W3V  ||  sW := W2V^T  ||  sH1 := sig(h1V)  ||  cvec
        for (int i = tid; i < TB * 32; i += NTH) {
            int r = i >> 5, c4 = (i & 31) << 2;
            float4 h = *(const float4*)&sH2[r * HS + c4];
            float4 w = *(const float4*)&sW3V[c4];
            float4 ov;
            ov.x = (1.f - __expf(-h.x)) * w.x;
            ov.y = (1.f - __expf(-h.y)) * w.y;
            ov.z = (1.f - __expf(-h.z)) * w.z;
            ov.w = (1.f - __expf(-h.w)) * w.w;
            *(float4*)&sU[r * HS + c4] = ov;
        }
        streamWT(gW2V);
        sigConvert(sH1);
        if (tid < TB) {
            const int r = tid;
            #pragma unroll
            for (int i = 0; i < 6; i++) {
                float ms = 0.f;
                #pragma unroll
                for (int j = 0; j < 6; j++) ms += sM[r * 36 + i * 6 + j] * svec[j];
                cvec[i] = Aacc[i] + ms - Cacc[i];
            }
        }
        __syncthreads();

        // R10: u1g = sig1V * (u2g @ W2V^T)  -> sH2 (no alias)
        bigGemm(sU, nullptr, sH2, sH1, false);
        __syncthreads();

        // R11: gx[d] = sum_k u1g[k] * W1V[d][k]  (lanes 0..11)
        if (lane < 12) {
            float acc[8];
            #pragma unroll
            for (int rr = 0; rr < 8; rr++) acc[rr] = 0.f;
            #pragma unroll 2
            for (int k = 0; k < 128; k += 4) {
                float4 wv = *(const float4*)&sW1V[lane * SWS + k];
                #pragma unroll
                for (int rr = 0; rr < 8; rr++) {
                    float4 av = *(const float4*)&sH2[(r0 + rr) * HS + k];
                    acc[rr] += av.x * wv.x + av.y * wv.y
                             + av.z * wv.z + av.w * wv.w;
                }
            }
            #pragma unroll
            for (int rr = 0; rr < 8; rr++) sDY[(r0 + rr) * 21 + lane] = acc[rr];
        }
        __syncthreads();

        // R12: rhs, triangular solves -> qddot ; stage-0 state update
        if (tid < TB) {
            const int r = tid;
            const float* Mp = sM + r * 36;
            float rhs[6];
            #pragma unroll
            for (int i = 0; i < 6; i++) {
                float gx0 = sDY[r * 21 + 2 * i];
                float gx1 = sDY[r * 21 + 2 * i + 1];
                float dv = -sX[r * 12 + 2 * i + 1] * gx0
                         +  sX[r * 12 + 2 * i]     * gx1;
                rhs[i] = sA[r * 6 + i] - cvec[i] - dv;
            }
            float yv[6];
            #pragma unroll
            for (int i = 0; i < 6; i++) {
                float s2 = rhs[i];
                #pragma unroll
                for (int j = 0; j < 6; j++) if (j < i) s2 -= Mp[i * 6 + j] * yv[j];
                yv[i] = s2 / Mp[i * 6 + i];
            }
            float zv[6];
            #pragma unroll
            for (int ii = 5; ii >= 0; ii--) {
                float s2 = yv[ii];
                #pragma unroll
                for (int j = 0; j < 6; j++) if (j > ii) s2 -= Mp[j * 6 + ii] * zv[j];
                zv[ii] = s2 / Mp[ii * 6 + ii];
            }
            if (stage == 0) {
                #pragma unroll
                for (int i = 0; i < 6; i++) {
                    sK1[r * 6 + i] = zv[i];
                    float q0  = sQ[r * 6 + i];
                    float qd0 = sQd[r * 6 + i];
                    sQ[r * 6 + i]  = q0  + ADT * qd0;
                    sQd[r * 6 + i] = qd0 + ADT * zv[i];
                }
            } else {
                #pragma unroll
                for (int i = 0; i < 6; i++) sQdd[r * 6 + i] = zv[i];
            }
        }
        __syncthreads();
    }

    // ---- RK2 combine + passthrough tail ----
    for (int i = tid; i < TB * 18; i += NTH) {
        int r = i / 18, c = i - 18 * r;
        int g = base + r;
        if (g < B) {
            float v;
            if (c < 6) {
                v = o[g * 18 + c] + 0.02f * (0.25f * o[g * 18 + 6 + c] + 0.75f * sQd[r * 6 + c]);
            } else if (c < 12) {
                int j = c - 6;
                v = o[g * 18 + c] + 0.02f * (0.25f * sK1[r * 6 + j] + 0.75f * sQdd[r * 6 + j]);
            } else {
                v = o[g * 18 + c];
            }
            outp[g * 18 + c] = v;
        }
    }
}

extern "C" void kernel_launch(void* const* d_in, const int* in_sizes, int n_in,
                              void* d_out, int out_size) {
    const float* o    = (const float*)d_in[0];
    const float* a    = (const float*)d_in[1];
    const float* W1L  = (const float*)d_in[2];
    const float* b1L  = (const float*)d_in[3];
    const float* W2L  = (const float*)d_in[4];
    const float* b2L  = (const float*)d_in[5];
    const float* W3L  = (const float*)d_in[6];
    const float* b3L  = (const float*)d_in[7];
    const float* W1V  = (const float*)d_in[8];
    const float* b1V  = (const float*)d_in[9];
    const float* W2V  = (const float*)d_in[10];
    const float* b2V  = (const float*)d_in[11];
    const float* W3V  = (const float*)d_in[12];
    float* outp = (float*)d_out;

    int B = in_sizes[0] / 18;
    int grid = (B + TB - 1) / TB;
    size_t smem = (size_t)SMEM_FLOATS * sizeof(float);
    cudaFuncSetAttribute(lnn6dof_kernel,
                         cudaFuncAttributeMaxDynamicSharedMemorySize, (int)smem);
    lnn6dof_kernel<<<grid, NTH, smem>>>(o, a, W1L, b1L, W2L, b2L, W3L, b3L,
                                        W1V, b1V, W2V, b2V, W3V, outp, B);
}

// round 4
// speedup vs baseline: 1.0010x; 1.0010x over previous
#include <cuda_runtime.h>
#include <math.h>

#define NTH 256
#define TB  64
#define SWS 132   // weight smem stride (floats)
#define HS  132   // activation smem stride (floats)

// ---- smem layout (float offsets) ----
#define OFF_W    0
#define OFF_H1   (OFF_W   + 128*SWS)
#define OFF_H2   (OFF_H1  + TB*HS)
#define OFF_U    (OFF_H2  + TB*HS)
#define OFF_W1L  (OFF_U   + TB*HS)
#define OFF_W1V  (OFF_W1L + 12*SWS)
#define OFF_W3L  (OFF_W1V + 12*SWS)
#define OFF_W3V  (OFF_W3L + 128*21)
#define OFF_B1L  (OFF_W3V + 128)
#define OFF_B2L  (OFF_B1L + 128)
#define OFF_B3L  (OFF_B2L + 128)
#define OFF_B1V  (OFF_B3L + 24)
#define OFF_B2V  (OFF_B1V + 128)
#define OFF_X    (OFF_B2V + 128)
#define OFF_Q    (OFF_X   + TB*12)
#define OFF_QD   (OFF_Q   + TB*6)
#define OFF_A    (OFF_QD  + TB*6)
#define OFF_K1   (OFF_A   + TB*6)
#define OFF_M    (OFF_K1  + TB*6)
#define OFF_L    (OFF_M   + TB*36)
#define OFF_DY   (OFF_L   + TB*21)
#define OFF_QDD  (OFF_DY  + TB*21)
#define SMEM_FLOATS (OFF_QDD + TB*6)

static __device__ __forceinline__ float softplusf(float z) {
    return fmaxf(z, 0.0f) + __logf(1.0f + __expf(-fabsf(z)));
}
// sigmoid(z) given h = softplus(z):  sigma = 1 - exp(-h)   (h >= 0)
static __device__ __forceinline__ float sig_from_h(float h) {
    return 1.0f - __expf(-h);
}
static __device__ __forceinline__ float f4c(const float4& v, int k) {
    return k == 0 ? v.x : k == 1 ? v.y : k == 2 ? v.z : v.w;
}

extern "C" __global__ void __launch_bounds__(NTH, 1)
lnn6dof_kernel(const float* __restrict__ o,    const float* __restrict__ ain,
               const float* __restrict__ gW1L, const float* __restrict__ gb1L,
               const float* __restrict__ gW2L, const float* __restrict__ gb2L,
               const float* __restrict__ gW3L, const float* __restrict__ gb3L,
               const float* __restrict__ gW1V, const float* __restrict__ gb1V,
               const float* __restrict__ gW2V, const float* __restrict__ gb2V,
               const float* __restrict__ gW3V,
               float* __restrict__ outp, int B)
{
    extern __shared__ float sm[];
    float* sW   = sm + OFF_W;
    float* sH1  = sm + OFF_H1;
    float* sH2  = sm + OFF_H2;
    float* sU   = sm + OFF_U;
    float* sW1L = sm + OFF_W1L;
    float* sW1V = sm + OFF_W1V;
    float* sW3L = sm + OFF_W3L;
    float* sW3V = sm + OFF_W3V;
    float* sB1L = sm + OFF_B1L;
    float* sB2L = sm + OFF_B2L;
    float* sB3L = sm + OFF_B3L;
    float* sB1V = sm + OFF_B1V;
    float* sB2V = sm + OFF_B2V;
    float* sX   = sm + OFF_X;
    float* sQ   = sm + OFF_Q;
    float* sQd  = sm + OFF_QD;
    float* sA   = sm + OFF_A;
    float* sK1  = sm + OFF_K1;
    float* sM   = sm + OFF_M;
    float* sL   = sm + OFF_L;
    float* sDY  = sm + OFF_DY;
    float* sQdd = sm + OFF_QDD;

    const int tid  = threadIdx.x;
    const int lane = tid & 31;
    const int r0   = (tid >> 5) * 8;   // warp's first local row
    const int c0   = lane * 4;         // lane's first output col

    // ---- persistent small weights ----
    for (int i = tid; i < 12 * 128; i += NTH) {
        int r = i >> 7, c = i & 127;
        sW1L[r * SWS + c] = gW1L[i];
        sW1V[r * SWS + c] = gW1V[i];
    }
    for (int i = tid; i < 128 * 21; i += NTH) sW3L[i] = gW3L[i];
    for (int i = tid; i < 128; i += NTH) {
        sW3V[i] = gW3V[i];
        sB1L[i] = gb1L[i]; sB2L[i] = gb2L[i];
        sB1V[i] = gb1V[i]; sB2V[i] = gb2V[i];
    }
    if (tid < 21) sB3L[tid] = gb3L[tid];

    const int base = blockIdx.x * TB;
    for (int i = tid; i < TB * 6; i += NTH) {
        int r = i / 6, c = i - 6 * r;
        int g = base + r; if (g > B - 1) g = B - 1;
        sQ[i]  = o[g * 18 + c];
        sQd[i] = o[g * 18 + 6 + c];
        sA[i]  = ain[g * 6 + c];
    }
    __syncthreads();

    // ---------- helpers (NO trailing sync inside; caller syncs) ----------
    // big GEMM: Out[r][c] = post( Ain[r][:] @ sW[:, c] (+ bias) )
    // post: mulSrc ? mulSrc[idx]*acc : softplus(acc)     (mulSrc already sigma!)
    auto bigGemm = [&](const float* Ain, const float* bias, float* Out,
                       const float* mulSrc, bool inplace) {
        float acc[8][4];
        if (bias) {
            float4 bv = *(const float4*)&bias[c0];
            #pragma unroll
            for (int rr = 0; rr < 8; rr++) {
                acc[rr][0] = bv.x; acc[rr][1] = bv.y;
                acc[rr][2] = bv.z; acc[rr][3] = bv.w;
            }
        } else {
            #pragma unroll
            for (int rr = 0; rr < 8; rr++)
                acc[rr][0] = acc[rr][1] = acc[rr][2] = acc[rr][3] = 0.f;
        }
        #pragma unroll 2
        for (int k = 0; k < 128; k += 4) {
            float4 av[8];
            #pragma unroll
            for (int rr = 0; rr < 8; rr++)
                av[rr] = *(const float4*)&Ain[(r0 + rr) * HS + k];
            #pragma unroll
            for (int kk = 0; kk < 4; kk++) {
                float4 wv = *(const float4*)&sW[(k + kk) * SWS + c0];
                #pragma unroll
                for (int rr = 0; rr < 8; rr++) {
                    float a = f4c(av[rr], kk);
                    acc[rr][0] += a * wv.x;
                    acc[rr][1] += a * wv.y;
                    acc[rr][2] += a * wv.z;
                    acc[rr][3] += a * wv.w;
                }
            }
        }
        if (inplace) __syncthreads();   // everyone done reading before overwrite
        #pragma unroll
        for (int rr = 0; rr < 8; rr++) {
            int rb = (r0 + rr) * HS + c0;
            float4 ov;
            if (mulSrc) {
                float4 mv = *(const float4*)&mulSrc[rb];
                ov.x = acc[rr][0] * mv.x; ov.y = acc[rr][1] * mv.y;
                ov.z = acc[rr][2] * mv.z; ov.w = acc[rr][3] * mv.w;
            } else {
                ov.x = softplusf(acc[rr][0]); ov.y = softplusf(acc[rr][1]);
                ov.z = softplusf(acc[rr][2]); ov.w = softplusf(acc[rr][3]);
            }
            *(float4*)&Out[rb] = ov;
        }
    };

    // K=12 GEMM from sX: Out = softplus(sX @ Wsm + bias)
    auto smallGemm = [&](const float* Wsm, const float* bias, float* Out) {
        float acc[8][4];
        float4 bv = *(const float4*)&bias[c0];
        #pragma unroll
        for (int rr = 0; rr < 8; rr++) {
            acc[rr][0] = bv.x; acc[rr][1] = bv.y;
            acc[rr][2] = bv.z; acc[rr][3] = bv.w;
        }
        #pragma unroll
        for (int k = 0; k < 12; k += 4) {
            float4 av[8];
            #pragma unroll
            for (int rr = 0; rr < 8; rr++)
                av[rr] = *(const float4*)&sX[(r0 + rr) * 12 + k];
            #pragma unroll
            for (int kk = 0; kk < 4; kk++) {
                float4 wv = *(const float4*)&Wsm[(k + kk) * SWS + c0];
                #pragma unroll
                for (int rr = 0; rr < 8; rr++) {
                    float a = f4c(av[rr], kk);
                    acc[rr][0] += a * wv.x; acc[rr][1] += a * wv.y;
                    acc[rr][2] += a * wv.z; acc[rr][3] += a * wv.w;
                }
            }
        }
        #pragma unroll
        for (int rr = 0; rr < 8; rr++) {
            int rb = (r0 + rr) * HS + c0;
            float4 ov;
            ov.x = softplusf(acc[rr][0]); ov.y = softplusf(acc[rr][1]);
            ov.z = softplusf(acc[rr][2]); ov.w = softplusf(acc[rr][3]);
            *(float4*)&Out[rb] = ov;
        }
    };

    // 128->21 GEMM with W3L : sDY[r*21+l] (lanes 0..20)
    auto mini21 = [&](const float* Ain, const float* bias) {
        if (lane < 21) {
            float acc[8];
            float b = bias ? bias[lane] : 0.f;
            #pragma unroll
            for (int rr = 0; rr < 8; rr++) acc[rr] = b;
            #pragma unroll 2
            for (int k = 0; k < 128; k += 4) {
                float4 av[8];
                #pragma unroll
                for (int rr = 0; rr < 8; rr++)
                    av[rr] = *(const float4*)&Ain[(r0 + rr) * HS + k];
                #pragma unroll
                for (int kk = 0; kk < 4; kk++) {
                    float wv = sW3L[(k + kk) * 21 + lane];
                    #pragma unroll
                    for (int rr = 0; rr < 8; rr++)
                        acc[rr] += f4c(av[rr], kk) * wv;
                }
            }
            #pragma unroll
            for (int rr = 0; rr < 8; rr++) sDY[(r0 + rr) * 21 + lane] = acc[rr];
        }
    };

    // tangent layer-1 input: sU = sig1 * (cq*W1L[2d+1] - sq*W1L[2d])
    auto buildU1 = [&](int d, int t, int nt) {
        for (int i = t; i < TB * 32; i += nt) {
            int r = i >> 5, c4 = (i & 31) << 2;
            float cq = sX[r * 12 + 2 * d];
            float sq = sX[r * 12 + 2 * d + 1];
            float4 w0 = *(const float4*)&sW1L[(2 * d) * SWS + c4];
            float4 w1 = *(const float4*)&sW1L[(2 * d + 1) * SWS + c4];
            float4 s1 = *(const float4*)&sH1[r * HS + c4];
            float4 ov;
            ov.x = s1.x * (cq * w1.x - sq * w0.x);
            ov.y = s1.y * (cq * w1.y - sq * w0.y);
            ov.z = s1.z * (cq * w1.z - sq * w0.z);
            ov.w = s1.w * (cq * w1.w - sq * w0.w);
            *(float4*)&sU[r * HS + c4] = ov;
        }
    };

    // convert h -> sigma(h) in place
    auto sigConvert = [&](float* P) {
        for (int i = tid; i < TB * 32; i += NTH) {
            float4* p = (float4*)&P[(i >> 5) * HS + ((i & 31) << 2)];
            float4 v = *p;
            v.x = 1.f - __expf(-v.x); v.y = 1.f - __expf(-v.y);
            v.z = 1.f - __expf(-v.z); v.w = 1.f - __expf(-v.w);
            *p = v;
        }
    };

    auto streamW = [&](const float* g) {     // row-major 128x128 -> sW
        for (int i = tid; i < 4096; i += NTH) {
            int r = i >> 5, c4 = (i & 31) << 2;
            *(float4*)&sW[r * SWS + c4] = *(const float4*)&g[i << 2];
        }
    };
    auto streamWT = [&](const float* g) {    // transposed -> sW
        for (int i = tid; i < 16384; i += NTH) {
            int r = i >> 7, c = i & 127;
            sW[c * SWS + r] = g[i];
        }
    };

    const float ADT = (2.0f / 3.0f) * 0.02f;
    const int RO[6] = {0, 1, 3, 6, 10, 15};

    for (int stage = 0; stage < 2; ++stage) {
        float wv6[6], Aacc[6], svec[6], Cacc[6], cvec[6];

        // R1: trig features + stream W2L
        for (int i = tid; i < TB * 6; i += NTH) {
            int r = i / 6, j = i - 6 * r;
            float sv, cv; __sincosf(sQ[i], &sv, &cv);
            sX[r * 12 + 2 * j]     = cv;
            sX[r * 12 + 2 * j + 1] = sv;
        }
        streamW(gW2L);
        __syncthreads();

        // R2: h1 = softplus(x @ W1L + b1L)
        smallGemm(sW1L, sB1L, sH1);
        __syncthreads();

        // R3: h2 = softplus(h1 @ W2L + b2L)
        bigGemm(sH1, sB2L, sH2, nullptr, false);
        __syncthreads();

        // R4: y = h2 @ W3L + b3L  ;  sH1 := sigma(h1)
        mini21(sH2, sB3L);
        sigConvert(sH1);
        __syncthreads();

        // R5: per-row L, M, w  ||  sH2 := sigma(h2)  ||  u1(dir 0)
        if (tid < TB) {
            const int r = tid;
            const float* y = sDY + r * 21;
            float* Lp = sL + r * 21;
            #pragma unroll
            for (int t = 0; t < 21; t++) Lp[t] = y[t];
            float* Mp = sM + r * 36;
            #pragma unroll
            for (int i = 0; i < 6; i++) {
                #pragma unroll
                for (int j = 0; j <= i; j++) {
                    float s2 = 0.f;
                    #pragma unroll
                    for (int k = 0; k <= j; k++)
                        s2 += Lp[RO[i] + k] * Lp[RO[j] + k];
                    if (i == j) s2 += 1e-6f;
                    Mp[i * 6 + j] = s2; Mp[j * 6 + i] = s2;
                }
            }
            #pragma unroll
            for (int i = 0; i < 6; i++) {
                float s2 = 0.f;
                #pragma unroll
                for (int j = 0; j < 6; j++) s2 += Mp[i * 6 + j] * sQd[r * 6 + j];
                wv6[i] = s2; Aacc[i] = 0.f; svec[i] = 0.f;
            }
        }
        sigConvert(sH2);
        if (tid >= 64) buildU1(0, tid - 64, NTH - 64);
        __syncthreads();

        // ---- 6 tangent directions ----
        for (int dir = 0; dir < 6; ++dir) {
            bigGemm(sU, nullptr, sU, sH2, true);   // u2 = sig2*(u1@W2L), in place
            __syncthreads();
            mini21(sU, nullptr);                   // dy
            if (dir == 5) streamW(gW2V);           // sW := W2V (W2L done)
            __syncthreads();

            if (tid < TB) {                        // epilogue(dir)
                const int r = tid;
                const float* dy  = sDY + r * 21;
                const float* Lp  = sL  + r * 21;
                const float* qdr = sQd + r * 6;
                float D[6][6];
                #pragma unroll
                for (int i = 0; i < 6; i++) {
                    #pragma unroll
                    for (int j = 0; j <= i; j++) {
                        float s2 = 0.f;
                        #pragma unroll
                        for (int k = 0; k <= j; k++)
                            s2 += dy[RO[i] + k] * Lp[RO[j] + k]
                                + Lp[RO[i] + k] * dy[RO[j] + k];
                        D[i][j] = s2; D[j][i] = s2;
                    }
                }
                float qdd = qdr[dir];
                float cdot = 0.f;
                #pragma unroll
                for (int i = 0; i < 6; i++) {
                    float v1 = 0.f, v2 = 0.f;
                    #pragma unroll
                    for (int j = 0; j < 6; j++) {
                        v1 += D[i][j] * wv6[j];
                        v2 += D[i][j] * qdr[j];
                    }
                    Aacc[i] += qdd * v1;
                    svec[i] += qdd * v2;
                    cdot    += qdr[i] * v1;
                }
                Cacc[dir] = cdot;
            }
            if (dir < 5) {
                if (tid >= 64) buildU1(dir + 1, tid - 64, NTH - 64);
            } else {
                smallGemm(sW1V, sB1V, sH1);        // h1V (all threads)
            }
            __syncthreads();
        }

        // h2V
        bigGemm(sH1, sB2V, sH2, nullptr, false);
        __syncthreads();

        // R9: u2g = sig(h2V)*W3V  ||  sW := W2V^T  ||  sH1 := sig(h1V)  ||  cvec
        for (int i = tid; i < TB * 32; i += NTH) {
            int r = i >> 5, c4 = (i & 31) << 2;
            float4 h = *(const float4*)&sH2[r * HS + c4];
            float4 w = *(const float4*)&sW3V[c4];
            float4 ov;
            ov.x = (1.f - __expf(-h.x)) * w.x;
            ov.y = (1.f - __expf(-h.y)) * w.y;
            ov.z = (1.f - __expf(-h.z)) * w.z;
            ov.w = (1.f - __expf(-h.w)) * w.w;
            *(float4*)&sU[r * HS + c4] = ov;
        }
        streamWT(gW2V);
        sigConvert(sH1);
        if (tid < TB) {
            const int r = tid;
            #pragma unroll
            for (int i = 0; i < 6; i++) {
                float ms = 0.f;
                #pragma unroll
                for (int j = 0; j < 6; j++) ms += sM[r * 36 + i * 6 + j] * svec[j];
                cvec[i] = Aacc[i] + ms - Cacc[i];
            }
        }
        __syncthreads();

        // R10: u1g = sig1V * (u2g @ W2V^T)  -> sH2 (no alias)
        bigGemm(sU, nullptr, sH2, sH1, false);
        __syncthreads();

        // R11: gx[d] = sum_k u1g[k] * W1V[d][k]  (lanes 0..11)
        if (lane < 12) {
            float acc[8];
            #pragma unroll
            for (int rr = 0; rr < 8; rr++) acc[rr] = 0.f;
            #pragma unroll 2
            for (int k = 0; k < 128; k += 4) {
                float4 wv = *(const float4*)&sW1V[lane * SWS + k];
                #pragma unroll
                for (int rr = 0; rr < 8; rr++) {
                    float4 av = *(const float4*)&sH2[(r0 + rr) * HS + k];
                    acc[rr] += av.x * wv.x + av.y * wv.y
                             + av.z * wv.z + av.w * wv.w;
                }
            }
            #pragma unroll
            for (int rr = 0; rr < 8; rr++) sDY[(r0 + rr) * 21 + lane] = acc[rr];
        }
        __syncthreads();

        // R12: rhs, triangular solves -> qddot ; stage-0 state update
        if (tid < TB) {
            const int r = tid;
            const float* Mp = sM + r * 36;
            float rhs[6];
            #pragma unroll
            for (int i = 0; i < 6; i++) {
                float gx0 = sDY[r * 21 + 2 * i];
                float gx1 = sDY[r * 21 + 2 * i + 1];
                float dv = -sX[r * 12 + 2 * i + 1] * gx0
                         +  sX[r * 12 + 2 * i]     * gx1;
                rhs[i] = sA[r * 6 + i] - cvec[i] - dv;
            }
            float yv[6];
            #pragma unroll
            for (int i = 0; i < 6; i++) {
                float s2 = rhs[i];
                #pragma unroll
                for (int j = 0; j < 6; j++) if (j < i) s2 -= Mp[i * 6 + j] * yv[j];
                yv[i] = s2 / Mp[i * 6 + i];
            }
            float zv[6];
            #pragma unroll
            for (int ii = 5; ii >= 0; ii--) {
                float s2 = yv[ii];
                #pragma unroll
                for (int j = 0; j < 6; j++) if (j > ii) s2 -= Mp[j * 6 + ii] * zv[j];
                zv[ii] = s2 / Mp[ii * 6 + ii];
            }
            if (stage == 0) {
                #pragma unroll
                for (int i = 0; i < 6; i++) {
                    sK1[r * 6 + i] = zv[i];
                    float q0  = sQ[r * 6 + i];
                    float qd0 = sQd[r * 6 + i];
                    sQ[r * 6 + i]  = q0  + ADT * qd0;
                    sQd[r * 6 + i] = qd0 + ADT * zv[i];
                }
            } else {
                #pragma unroll
                for (int i = 0; i < 6; i++) sQdd[r * 6 + i] = zv[i];
            }
        }
        __syncthreads();
    }

    // ---- RK2 combine + passthrough tail ----
    for (int i = tid; i < TB * 18; i += NTH) {
        int r = i / 18, c = i - 18 * r;
        int g = base + r;
        if (g < B) {
            float v;
            if (c < 6) {
                v = o[g * 18 + c] + 0.02f * (0.25f * o[g * 18 + 6 + c] + 0.75f * sQd[r * 6 + c]);
            } else if (c < 12) {
                int j = c - 6;
                v = o[g * 18 + c] + 0.02f * (0.25f * sK1[r * 6 + j] + 0.75f * sQdd[r * 6 + j]);
            } else {
                v = o[g * 18 + c];
            }
            outp[g * 18 + c] = v;
        }
    }
}

extern "C" void kernel_launch(void* const* d_in, const int* in_sizes, int n_in,
                              void* d_out, int out_size) {
    const float* o    = (const float*)d_in[0];
    const float* a    = (const float*)d_in[1];
    const float* W1L  = (const float*)d_in[2];
    const float* b1L  = (const float*)d_in[3];
    const float* W2L  = (const float*)d_in[4];
    const float* b2L  = (const float*)d_in[5];
    const float* W3L  = (const float*)d_in[6];
    const float* b3L  = (const float*)d_in[7];
    const float* W1V  = (const float*)d_in[8];
    const float* b1V  = (const float*)d_in[9];
    const float* W2V  = (const float*)d_in[10];
    const float* b2V  = (const float*)d_in[11];
    const float* W3V  = (const float*)d_in[12];
    float* outp = (float*)d_out;

    int B = in_sizes[0] / 18;
    int grid = (B + TB - 1) / TB;
    size_t smem = (size_t)SMEM_FLOATS * sizeof(float);
    cudaFuncSetAttribute(lnn6dof_kernel,
                         cudaFuncAttributeMaxDynamicSharedMemorySize, (int)smem);
    lnn6dof_kernel<<<grid, NTH, smem>>>(o, a, W1L, b1L, W2L, b2L, W3L, b3L,
                                        W1V, b1V, W2V, b2V, W3V, outp, B);
}